// round 15
// baseline (speedup 1.0000x reference)
#include <cuda_runtime.h>

#define BB 256
#define NN 256
#define KNNK 4
#define NPTS (BB*NN)

// ---------------- device scratch ----------------
__device__ float g_a[NPTS*192];
__device__ float g_b[NPTS*192];
__device__ float g_c[NPTS*192];
__device__ float g_d[NPTS*192];
__device__ float g_h[NPTS*192];
__device__ float g_pool[BB*768];
__device__ int   g_idx[NPTS*KNNK];

// ---------------- helpers ----------------
typedef unsigned long long ull;

__device__ __forceinline__ float leakyf(float x) { return x >= 0.f ? x : 0.01f * x; }

__device__ __forceinline__ ull pack2(float x) {
    ull r; unsigned u = __float_as_uint(x);
    asm("mov.b64 %0, {%1, %1};" : "=l"(r) : "r"(u));
    return r;
}
__device__ __forceinline__ void fma2(ull& d, ull a, ull b) {
    asm("fma.rn.f32x2 %0, %1, %2, %0;" : "+l"(d) : "l"(a), "l"(b));
}
__device__ __forceinline__ ull add2(ull a, ull b) {
    ull r;
    asm("add.rn.f32x2 %0, %1, %2;" : "=l"(r) : "l"(a), "l"(b));
    return r;
}
__device__ __forceinline__ float2 unpack2(ull v) {
    unsigned lo, hi;
    asm("mov.b64 {%0, %1}, %2;" : "=r"(lo), "=r"(hi) : "l"(v));
    return make_float2(__uint_as_float(lo), __uint_as_float(hi));
}

// ---------------- KNN (unchanged) ----------------
__global__ void knn_kernel(const float* __restrict__ pos, int stride, int* __restrict__ idx) {
    __shared__ float sx[NN], sy[NN], sz[NN];
    int b = blockIdx.x, i = threadIdx.x;
    const float* p = pos + ((size_t)b * NN + i) * stride;
    sx[i] = p[0]; sy[i] = p[1]; sz[i] = p[2];
    __syncthreads();
    float xi = sx[i], yi = sy[i], zi = sz[i];
    float d0 = 1e38f, d1 = 1e38f, d2 = 1e38f, d3 = 1e38f;
    int i0 = 0, i1 = 0, i2 = 0, i3 = 0;
    for (int j = 0; j < NN; j++) {
        if (j == i) continue;
        float dx = __fadd_rn(xi, -sx[j]);
        float dy = __fadd_rn(yi, -sy[j]);
        float dz = __fadd_rn(zi, -sz[j]);
        float d = __fmaf_rn(dz, dz, __fmaf_rn(dy, dy, __fmul_rn(dx, dx)));
        if (d < d3) {
            if (d < d2) {
                d3 = d2; i3 = i2;
                if (d < d1) {
                    d2 = d1; i2 = i1;
                    if (d < d0) { d1 = d0; i1 = i0; d0 = d; i0 = j; }
                    else        { d1 = d;  i1 = j; }
                } else { d2 = d; i2 = j; }
            } else { d3 = d; i3 = j; }
        }
    }
    int base = (b * NN + i) * KNNK;
    idx[base] = i0; idx[base + 1] = i1; idx[base + 2] = i2; idx[base + 3] = i3;
}

// ================= 16-edge class-pair GEMM, parametrized row stride =================
// Per-(edge,channel) math identical to R12/R13: p_l = sum over k≡l (mod 8) ascending,
// q_j = p_j + p_{j+4}, total = ((q0+q1)+(q2+q3)), sequential tail.
template<int K, int L, int RS>
__device__ __forceinline__ void pass2(ull pA[8], ull pB[8],
                                      const float* __restrict__ wj, int Hs,
                                      const float* __restrict__ smat) {
    #pragma unroll
    for (int i = 0; i < 8; i++) { pA[i] = 0; pB[i] = 0; }
    constexpr int KMAIN = K & ~7;
    #pragma unroll 2
    for (int kc = 0; kc < KMAIN; kc += 8) {
        float wa = __ldg(wj + (size_t)(kc + L) * Hs);
        float wb = __ldg(wj + (size_t)(kc + L + 4) * Hs);
        ull wpa = pack2(wa), wpb = pack2(wb);
        const ulonglong2* sa = (const ulonglong2*)(smat + (size_t)(kc + L) * RS);
        ulonglong2 a0 = sa[0], a1 = sa[1], a2 = sa[2], a3 = sa[3];
        fma2(pA[0], a0.x, wpa); fma2(pA[1], a0.y, wpa);
        fma2(pA[2], a1.x, wpa); fma2(pA[3], a1.y, wpa);
        fma2(pA[4], a2.x, wpa); fma2(pA[5], a2.y, wpa);
        fma2(pA[6], a3.x, wpa); fma2(pA[7], a3.y, wpa);
        const ulonglong2* sb = (const ulonglong2*)(smat + (size_t)(kc + L + 4) * RS);
        ulonglong2 b0 = sb[0], b1 = sb[1], b2 = sb[2], b3 = sb[3];
        fma2(pB[0], b0.x, wpb); fma2(pB[1], b0.y, wpb);
        fma2(pB[2], b1.x, wpb); fma2(pB[3], b1.y, wpb);
        fma2(pB[4], b2.x, wpb); fma2(pB[5], b2.y, wpb);
        fma2(pB[6], b3.x, wpb); fma2(pB[7], b3.y, wpb);
    }
}
template<int K, int RS>
__device__ __forceinline__ void gemm_col16(ull tot[8],
                                           const float* __restrict__ wj, int Hs,
                                           const float* __restrict__ smat) {
    ull c01[8], q[8], pA[8], pB[8];
    pass2<K, 0, RS>(pA, pB, wj, Hs, smat);
    #pragma unroll
    for (int i = 0; i < 8; i++) c01[i] = add2(pA[i], pB[i]);
    pass2<K, 1, RS>(pA, pB, wj, Hs, smat);
    #pragma unroll
    for (int i = 0; i < 8; i++) q[i] = add2(pA[i], pB[i]);
    #pragma unroll
    for (int i = 0; i < 8; i++) c01[i] = add2(c01[i], q[i]);
    pass2<K, 2, RS>(pA, pB, wj, Hs, smat);
    #pragma unroll
    for (int i = 0; i < 8; i++) q[i] = add2(pA[i], pB[i]);
    pass2<K, 3, RS>(pA, pB, wj, Hs, smat);
    #pragma unroll
    for (int i = 0; i < 8; i++) pA[i] = add2(pA[i], pB[i]);
    #pragma unroll
    for (int i = 0; i < 8; i++) q[i] = add2(q[i], pA[i]);
    #pragma unroll
    for (int i = 0; i < 8; i++) tot[i] = add2(c01[i], q[i]);
    constexpr int KMAIN = K & ~7;
    #pragma unroll
    for (int k = KMAIN; k < K; k++) {
        ull wp = pack2(__ldg(wj + (size_t)k * Hs));
        const ulonglong2* sp = (const ulonglong2*)(smat + (size_t)k * RS);
        ulonglong2 v0 = sp[0], v1 = sp[1], v2 = sp[2], v3 = sp[3];
        fma2(tot[0], v0.x, wp); fma2(tot[1], v0.y, wp);
        fma2(tot[2], v1.x, wp); fma2(tot[3], v1.y, wp);
        fma2(tot[4], v2.x, wp); fma2(tot[5], v2.y, wp);
        fma2(tot[6], v3.x, wp); fma2(tot[7], v3.y, wp);
    }
}

// ===== split GEMM1 pass (FIN=192), 16-edge half of an 8-point block =====
// sxip = sxi + 4h (points 4h..4h+3, row stride 8); sdxp = sdx + 16h (row stride 32).
// Chain per class l: k=l..184 over xi (per-point), continue k=192+l.. over dx (per-edge).
// Identical op sequence to R13's pass_split.
template<int L>
__device__ __forceinline__ void pass_split(ull pA[8], ull pB[8],
                                           const float* __restrict__ wj, int Hs,
                                           const float* __restrict__ sxip,
                                           const float* __restrict__ sdxp) {
    ull a01 = 0, a23 = 0, b01 = 0, b23 = 0;
    #pragma unroll 4
    for (int kc = 0; kc < 192; kc += 8) {
        float wa = __ldg(wj + (size_t)(kc + L) * Hs);
        float wb = __ldg(wj + (size_t)(kc + L + 4) * Hs);
        ull wpa = pack2(wa), wpb = pack2(wb);
        const ull* xa = (const ull*)(sxip + (kc + L) * 8);
        fma2(a01, xa[0], wpa); fma2(a23, xa[1], wpa);
        const ull* xb = (const ull*)(sxip + (kc + L + 4) * 8);
        fma2(b01, xb[0], wpb); fma2(b23, xb[1], wpb);
    }
    {
        float2 v01 = unpack2(a01), v23 = unpack2(a23);
        pA[0] = pack2(v01.x); pA[1] = pack2(v01.x);
        pA[2] = pack2(v01.y); pA[3] = pack2(v01.y);
        pA[4] = pack2(v23.x); pA[5] = pack2(v23.x);
        pA[6] = pack2(v23.y); pA[7] = pack2(v23.y);
        float2 u01 = unpack2(b01), u23 = unpack2(b23);
        pB[0] = pack2(u01.x); pB[1] = pack2(u01.x);
        pB[2] = pack2(u01.y); pB[3] = pack2(u01.y);
        pB[4] = pack2(u23.x); pB[5] = pack2(u23.x);
        pB[6] = pack2(u23.y); pB[7] = pack2(u23.y);
    }
    const float* wj2 = wj + (size_t)192 * Hs;
    #pragma unroll 2
    for (int kc = 0; kc < 192; kc += 8) {
        float wa = __ldg(wj2 + (size_t)(kc + L) * Hs);
        float wb = __ldg(wj2 + (size_t)(kc + L + 4) * Hs);
        ull wpa = pack2(wa), wpb = pack2(wb);
        const ulonglong2* sa = (const ulonglong2*)(sdxp + (size_t)(kc + L) * 32);
        ulonglong2 a0 = sa[0], a1 = sa[1], a2 = sa[2], a3 = sa[3];
        fma2(pA[0], a0.x, wpa); fma2(pA[1], a0.y, wpa);
        fma2(pA[2], a1.x, wpa); fma2(pA[3], a1.y, wpa);
        fma2(pA[4], a2.x, wpa); fma2(pA[5], a2.y, wpa);
        fma2(pA[6], a3.x, wpa); fma2(pA[7], a3.y, wpa);
        const ulonglong2* sb = (const ulonglong2*)(sdxp + (size_t)(kc + L + 4) * 32);
        ulonglong2 b0 = sb[0], b1 = sb[1], b2 = sb[2], b3 = sb[3];
        fma2(pB[0], b0.x, wpb); fma2(pB[1], b0.y, wpb);
        fma2(pB[2], b1.x, wpb); fma2(pB[3], b1.y, wpb);
        fma2(pB[4], b2.x, wpb); fma2(pB[5], b2.y, wpb);
        fma2(pB[6], b3.x, wpb); fma2(pB[7], b3.y, wpb);
    }
}
__device__ __forceinline__ void gemm1_split(ull tot[8],
                                            const float* __restrict__ wj, int Hs,
                                            const float* __restrict__ sxip,
                                            const float* __restrict__ sdxp) {
    ull c01[8], q[8], pA[8], pB[8];
    pass_split<0>(pA, pB, wj, Hs, sxip, sdxp);
    #pragma unroll
    for (int i = 0; i < 8; i++) c01[i] = add2(pA[i], pB[i]);
    pass_split<1>(pA, pB, wj, Hs, sxip, sdxp);
    #pragma unroll
    for (int i = 0; i < 8; i++) q[i] = add2(pA[i], pB[i]);
    #pragma unroll
    for (int i = 0; i < 8; i++) c01[i] = add2(c01[i], q[i]);
    pass_split<2>(pA, pB, wj, Hs, sxip, sdxp);
    #pragma unroll
    for (int i = 0; i < 8; i++) q[i] = add2(pA[i], pB[i]);
    pass_split<3>(pA, pB, wj, Hs, sxip, sdxp);
    #pragma unroll
    for (int i = 0; i < 8; i++) pA[i] = add2(pA[i], pB[i]);
    #pragma unroll
    for (int i = 0; i < 8; i++) q[i] = add2(q[i], pA[i]);
    #pragma unroll
    for (int i = 0; i < 8; i++) tot[i] = add2(c01[i], q[i]);
    // K=384: no tail
}

// ---------------- conv1 EdgeConv (FIN=4): R13 path, 256 threads ----------------
__global__ void __launch_bounds__(256, 2)
edgeconv1_kernel(const float* __restrict__ feat,
                 const int* __restrict__ idx,
                 const float* __restrict__ w1, const float* __restrict__ b1,
                 const float* __restrict__ w2, const float* __restrict__ b2,
                 float* __restrict__ out) {
    constexpr int FIN = 4, H = 96, Cout = 192, F2 = 8;
    __shared__ __align__(16) float sf[F2 * 16];
    __shared__ __align__(16) float s[H * 16];
    __shared__ int nb[16];
    int m0 = blockIdx.x * 4;
    int tid = threadIdx.x;
    if (tid < 16) {
        int p = tid >> 2;
        int m = m0 + p;
        nb[tid] = (m & ~(NN - 1)) + idx[m * KNNK + (tid & 3)];
    }
    __syncthreads();
    if (tid < F2 * 16) {
        int e = tid & 15, k = tid >> 4;
        int p = e >> 2;
        float v;
        if (k < FIN) v = feat[(size_t)(m0 + p) * FIN + k];
        else {
            int kk = k - FIN;
            v = __fadd_rn(feat[(size_t)nb[e] * FIN + kk], -feat[(size_t)(m0 + p) * FIN + kk]);
        }
        sf[tid] = v;
    }
    __syncthreads();
    if (tid < H) {
        int j = tid;
        ull tot[8];
        gemm_col16<F2, 16>(tot, w1 + j, H, sf);
        float bb = b1[j];
        #pragma unroll
        for (int u = 0; u < 4; u++) {
            float2 r0 = unpack2(tot[2 * u]);
            float2 r1 = unpack2(tot[2 * u + 1]);
            *(float4*)(s + j * 16 + 4 * u) =
                make_float4(leakyf(__fadd_rn(r0.x, bb)), leakyf(__fadd_rn(r0.y, bb)),
                            leakyf(__fadd_rn(r1.x, bb)), leakyf(__fadd_rn(r1.y, bb)));
        }
    }
    __syncthreads();
    if (tid < Cout) {
        int o = tid;
        ull tot[8];
        gemm_col16<H, 16>(tot, w2 + o, Cout, s);
        float bb = b2[o];
        #pragma unroll
        for (int p = 0; p < 4; p++) {
            float2 x0 = unpack2(tot[2 * p]);
            float2 x1 = unpack2(tot[2 * p + 1]);
            float r = leakyf(x0.x + bb) + leakyf(x0.y + bb) +
                      leakyf(x1.x + bb) + leakyf(x1.y + bb);
            out[(size_t)(m0 + p) * Cout + o] = r;
        }
    }
}

// ---------------- heavy EdgeConv: 8 points (32 edges)/block, 512 threads ----------------
// thread = (channel j = tid>>1, half h = tid&1); half h owns edges 16h..16h+15
// (points 4h..4h+3). Per-thread work is R13's exact shape -> bit-exact.
__global__ void __launch_bounds__(512, 1)
edgeconv_split_kernel(const float* __restrict__ feat,
                      const int* __restrict__ idx,
                      const float* __restrict__ w1, const float* __restrict__ b1,
                      const float* __restrict__ w2, const float* __restrict__ b2,
                      float* __restrict__ out) {
    constexpr int FIN = 192, H = 252, Cout = 192;
    extern __shared__ __align__(16) float dyn_[];
    float* sxi = dyn_;                      // [k*8  + p], 192*8
    float* sdx = dyn_ + FIN * 8;            // [k*32 + e], 192*32
    float* s   = sdx + FIN * 32;            // [j*32 + e], 252*32
    int*   nb  = (int*)(s + H * 32);        // [32]

    int m0 = blockIdx.x * 8;
    int tid = threadIdx.x;

    if (tid < 32) {
        int p = tid >> 2;
        int m = m0 + p;
        nb[tid] = (m & ~(NN - 1)) + idx[m * KNNK + (tid & 3)];
    }
    __syncthreads();

    for (int t = tid; t < FIN * 8; t += 512) {
        int p = t & 7, k = t >> 3;
        sxi[t] = feat[(size_t)(m0 + p) * FIN + k];
    }
    #pragma unroll 2
    for (int t = tid; t < FIN * 32; t += 512) {
        int e = t & 31, k = t >> 5;
        int p = e >> 2;
        sdx[t] = __fadd_rn(feat[(size_t)nb[e] * FIN + k], -feat[(size_t)(m0 + p) * FIN + k]);
    }
    __syncthreads();

    int j = tid >> 1, h = tid & 1;

    // GEMM 1 (split, 16-edge half)
    if (j < H) {
        ull tot[8];
        gemm1_split(tot, w1 + j, H, sxi + 4 * h, sdx + 16 * h);
        float bb = b1[j];
        #pragma unroll
        for (int u = 0; u < 4; u++) {
            float2 r0 = unpack2(tot[2 * u]);
            float2 r1 = unpack2(tot[2 * u + 1]);
            *(float4*)(s + j * 32 + 16 * h + 4 * u) =
                make_float4(leakyf(__fadd_rn(r0.x, bb)), leakyf(__fadd_rn(r0.y, bb)),
                            leakyf(__fadd_rn(r1.x, bb)), leakyf(__fadd_rn(r1.y, bb)));
        }
    }
    __syncthreads();

    // GEMM 2 (class-pair over H=252, 16-edge half); points 4h..4h+3
    if (j < Cout) {
        int o = j;
        ull tot[8];
        gemm_col16<H, 32>(tot, w2 + o, Cout, s + 16 * h);
        float bb = b2[o];
        #pragma unroll
        for (int pp = 0; pp < 4; pp++) {
            float2 x0 = unpack2(tot[2 * pp]);
            float2 x1 = unpack2(tot[2 * pp + 1]);
            float r = leakyf(x0.x + bb) + leakyf(x0.y + bb) +
                      leakyf(x1.x + bb) + leakyf(x1.y + bb);
            out[(size_t)(m0 + 4 * h + pp) * Cout + o] = r;
        }
    }
}

// ---------------- nn1+nn2 fused: 16 points/block, 256 threads (R13 verbatim) ----------------
__global__ void __launch_bounds__(256)
nn12_kernel(const float* __restrict__ x,
            const float* __restrict__ a, const float* __restrict__ b,
            const float* __restrict__ c, const float* __restrict__ d,
            const float* __restrict__ w1, const float* __restrict__ b1,
            const float* __restrict__ w2, const float* __restrict__ b2,
            float* __restrict__ hout) {
    extern __shared__ float dyn2_[];
    float* sin_ = dyn2_;
    float* sh1  = dyn2_ + 772 * 16;
    int m0 = blockIdx.x * 16;
    int tid = threadIdx.x;
    #pragma unroll 4
    for (int e = tid; e < 772 * 16; e += 256) {
        int ch = e >> 4, p = e & 15;
        size_t mp = (size_t)(m0 + p);
        float val;
        if (ch < 4)        val = x[mp * 4 + ch];
        else if (ch < 196) val = a[mp * 192 + (ch - 4)];
        else if (ch < 388) val = b[mp * 192 + (ch - 196)];
        else if (ch < 580) val = c[mp * 192 + (ch - 388)];
        else               val = d[mp * 192 + (ch - 580)];
        sin_[e] = val;
    }
    __syncthreads();
    if (tid < 252) {
        int j = tid;
        ull acc[8];
        #pragma unroll
        for (int i = 0; i < 8; i++) acc[i] = 0;
        #pragma unroll 2
        for (int k = 0; k < 772; k++) {
            ull wp = pack2(__ldg(w1 + (size_t)k * 252 + j));
            const ulonglong2* sp = (const ulonglong2*)(sin_ + k * 16);
            ulonglong2 s0 = sp[0], s1 = sp[1], s2 = sp[2], s3 = sp[3];
            fma2(acc[0], s0.x, wp); fma2(acc[1], s0.y, wp);
            fma2(acc[2], s1.x, wp); fma2(acc[3], s1.y, wp);
            fma2(acc[4], s2.x, wp); fma2(acc[5], s2.y, wp);
            fma2(acc[6], s3.x, wp); fma2(acc[7], s3.y, wp);
        }
        float bb = b1[j];
        #pragma unroll
        for (int u = 0; u < 4; u++) {
            float2 r0 = unpack2(acc[2 * u]);
            float2 r1 = unpack2(acc[2 * u + 1]);
            *(float4*)(sh1 + j * 16 + 4 * u) =
                make_float4(leakyf(r0.x + bb), leakyf(r0.y + bb),
                            leakyf(r1.x + bb), leakyf(r1.y + bb));
        }
    }
    __syncthreads();
    if (tid < 192) {
        int o = tid;
        ull acc[8];
        #pragma unroll
        for (int i = 0; i < 8; i++) acc[i] = 0;
        #pragma unroll 2
        for (int mm = 0; mm < 252; mm++) {
            ull wp = pack2(__ldg(w2 + mm * 192 + o));
            const ulonglong2* sp = (const ulonglong2*)(sh1 + mm * 16);
            ulonglong2 s0 = sp[0], s1 = sp[1], s2 = sp[2], s3 = sp[3];
            fma2(acc[0], s0.x, wp); fma2(acc[1], s0.y, wp);
            fma2(acc[2], s1.x, wp); fma2(acc[3], s1.y, wp);
            fma2(acc[4], s2.x, wp); fma2(acc[5], s2.y, wp);
            fma2(acc[6], s3.x, wp); fma2(acc[7], s3.y, wp);
        }
        float bb = b2[o];
        #pragma unroll
        for (int u = 0; u < 8; u++) {
            float2 r = unpack2(acc[u]);
            hout[(size_t)(m0 + 2 * u) * 192 + o]     = r.x + bb;
            hout[(size_t)(m0 + 2 * u + 1) * 192 + o] = r.y + bb;
        }
    }
}

// ---------------- pooling (unchanged) ----------------
__global__ void pool_kernel(const float* __restrict__ h, float* __restrict__ pooled) {
    int b = blockIdx.x, cch = threadIdx.x;
    const float* hp = h + (size_t)b * NN * 192 + cch;
    float mx = -1e38f, mn = 1e38f;
    double sm = 0.0;
    #pragma unroll 4
    for (int n = 0; n < NN; n++) {
        float v = hp[(size_t)n * 192];
        mx = fmaxf(mx, v); mn = fminf(mn, v);
        sm += (double)v;
    }
    float smf = (float)sm;
    float* pb = pooled + b * 768;
    pb[cch]       = leakyf(mx);
    pb[192 + cch] = leakyf(mn);
    pb[384 + cch] = leakyf(smf);
    pb[576 + cch] = leakyf(__fmul_rn(smf, (1.0f / 256.0f)));
}

// ---------------- final head (unchanged) ----------------
__global__ void final_kernel(const float* __restrict__ pooled,
                             const float* __restrict__ w3, const float* __restrict__ b3,
                             const float* __restrict__ w4, const float* __restrict__ b4,
                             float* __restrict__ out) {
    __shared__ float sp[768];
    __shared__ float smid[96];
    int b = blockIdx.x, tid = threadIdx.x;
    for (int e = tid; e < 768; e += blockDim.x) sp[e] = pooled[b * 768 + e];
    __syncthreads();
    if (tid < 96) {
        float acc = 0.f;
        for (int k = 0; k < 768; k++) acc = fmaf(sp[k], w3[k * 96 + tid], acc);
        smid[tid] = leakyf(acc + b3[tid]);
    }
    __syncthreads();
    if (tid == 0) {
        float sacc = 0.f;
        for (int k = 0; k < 96; k++) sacc = fmaf(smid[k], w4[k], sacc);
        out[b] = sacc + b4[0];
    }
}

// ---------------- launch ----------------
extern "C" void kernel_launch(void* const* d_in, const int* in_sizes, int n_in,
                              void* d_out, int out_size) {
    const float* x = (const float*)d_in[0];
    const float* prm[24];
    for (int i = 0; i < 24; i++) prm[i] = (const float*)d_in[i + 1];

    float *ga, *gb, *gc, *gd, *gh, *gp;
    int* gi;
    cudaGetSymbolAddress((void**)&ga, g_a);
    cudaGetSymbolAddress((void**)&gb, g_b);
    cudaGetSymbolAddress((void**)&gc, g_c);
    cudaGetSymbolAddress((void**)&gd, g_d);
    cudaGetSymbolAddress((void**)&gh, g_h);
    cudaGetSymbolAddress((void**)&gp, g_pool);
    cudaGetSymbolAddress((void**)&gi, g_idx);

    int ec_smem = (192 * 8 + 192 * 32 + 252 * 32) * 4 + 32 * 4;   // 63104 B
    cudaFuncSetAttribute(edgeconv_split_kernel, cudaFuncAttributeMaxDynamicSharedMemorySize, ec_smem);
    int nn12_smem = (772 + 252) * 16 * 4;   // 65536 B
    cudaFuncSetAttribute(nn12_kernel, cudaFuncAttributeMaxDynamicSharedMemorySize, nn12_smem);

    knn_kernel<<<BB, NN>>>(x, 4, gi);
    edgeconv1_kernel<<<NPTS / 4, 256>>>(x, gi, prm[0], prm[1], prm[2], prm[3], ga);

    knn_kernel<<<BB, NN>>>(ga, 192, gi);
    edgeconv_split_kernel<<<NPTS / 8, 512, ec_smem>>>(ga, gi, prm[4], prm[5], prm[6], prm[7], gb);

    knn_kernel<<<BB, NN>>>(gb, 192, gi);
    edgeconv_split_kernel<<<NPTS / 8, 512, ec_smem>>>(gb, gi, prm[8], prm[9], prm[10], prm[11], gc);

    knn_kernel<<<BB, NN>>>(gc, 192, gi);
    edgeconv_split_kernel<<<NPTS / 8, 512, ec_smem>>>(gc, gi, prm[12], prm[13], prm[14], prm[15], gd);

    nn12_kernel<<<NPTS / 16, 256, nn12_smem>>>(x, ga, gb, gc, gd,
                                               prm[16], prm[17], prm[18], prm[19], gh);

    pool_kernel<<<BB, 192>>>(gh, gp);
    final_kernel<<<BB, 128>>>(gp, prm[20], prm[21], prm[22], prm[23], (float*)d_out);
}

// round 16
// speedup vs baseline: 1.0863x; 1.0863x over previous
#include <cuda_runtime.h>

#define BB 256
#define NN 256
#define KNNK 4
#define NPTS (BB*NN)

// ---------------- device scratch ----------------
__device__ float g_a[NPTS*192];
__device__ float g_b[NPTS*192];
__device__ float g_c[NPTS*192];
__device__ float g_d[NPTS*192];
__device__ float g_h[NPTS*192];
__device__ float g_pool[BB*768];
__device__ int   g_idx[NPTS*KNNK];

// ---------------- helpers ----------------
typedef unsigned long long ull;

__device__ __forceinline__ float leakyf(float x) { return x >= 0.f ? x : 0.01f * x; }

__device__ __forceinline__ ull pack2(float x) {
    ull r; unsigned u = __float_as_uint(x);
    asm("mov.b64 %0, {%1, %1};" : "=l"(r) : "r"(u));
    return r;
}
__device__ __forceinline__ void fma2(ull& d, ull a, ull b) {
    asm("fma.rn.f32x2 %0, %1, %2, %0;" : "+l"(d) : "l"(a), "l"(b));
}
__device__ __forceinline__ ull add2(ull a, ull b) {
    ull r;
    asm("add.rn.f32x2 %0, %1, %2;" : "=l"(r) : "l"(a), "l"(b));
    return r;
}
__device__ __forceinline__ float2 unpack2(ull v) {
    unsigned lo, hi;
    asm("mov.b64 {%0, %1}, %2;" : "=r"(lo), "=r"(hi) : "l"(v));
    return make_float2(__uint_as_float(lo), __uint_as_float(hi));
}

// ---------------- KNN (unchanged) ----------------
__global__ void knn_kernel(const float* __restrict__ pos, int stride, int* __restrict__ idx) {
    __shared__ float sx[NN], sy[NN], sz[NN];
    int b = blockIdx.x, i = threadIdx.x;
    const float* p = pos + ((size_t)b * NN + i) * stride;
    sx[i] = p[0]; sy[i] = p[1]; sz[i] = p[2];
    __syncthreads();
    float xi = sx[i], yi = sy[i], zi = sz[i];
    float d0 = 1e38f, d1 = 1e38f, d2 = 1e38f, d3 = 1e38f;
    int i0 = 0, i1 = 0, i2 = 0, i3 = 0;
    for (int j = 0; j < NN; j++) {
        if (j == i) continue;
        float dx = __fadd_rn(xi, -sx[j]);
        float dy = __fadd_rn(yi, -sy[j]);
        float dz = __fadd_rn(zi, -sz[j]);
        float d = __fmaf_rn(dz, dz, __fmaf_rn(dy, dy, __fmul_rn(dx, dx)));
        if (d < d3) {
            if (d < d2) {
                d3 = d2; i3 = i2;
                if (d < d1) {
                    d2 = d1; i2 = i1;
                    if (d < d0) { d1 = d0; i1 = i0; d0 = d; i0 = j; }
                    else        { d1 = d;  i1 = j; }
                } else { d2 = d; i2 = j; }
            } else { d3 = d; i3 = j; }
        }
    }
    int base = (b * NN + i) * KNNK;
    idx[base] = i0; idx[base + 1] = i1; idx[base + 2] = i2; idx[base + 3] = i3;
}

// ================= 16-edge class-pair GEMM (conv1 only, R13 verbatim) =================
template<int K, int L>
__device__ __forceinline__ void pass2(ull pA[8], ull pB[8],
                                      const float* __restrict__ wj, int Hs,
                                      const float* __restrict__ smat) {
    #pragma unroll
    for (int i = 0; i < 8; i++) { pA[i] = 0; pB[i] = 0; }
    constexpr int KMAIN = K & ~7;
    #pragma unroll 2
    for (int kc = 0; kc < KMAIN; kc += 8) {
        float wa = __ldg(wj + (size_t)(kc + L) * Hs);
        float wb = __ldg(wj + (size_t)(kc + L + 4) * Hs);
        ull wpa = pack2(wa), wpb = pack2(wb);
        const ulonglong2* sa = (const ulonglong2*)(smat + (kc + L) * 16);
        ulonglong2 a0 = sa[0], a1 = sa[1], a2 = sa[2], a3 = sa[3];
        fma2(pA[0], a0.x, wpa); fma2(pA[1], a0.y, wpa);
        fma2(pA[2], a1.x, wpa); fma2(pA[3], a1.y, wpa);
        fma2(pA[4], a2.x, wpa); fma2(pA[5], a2.y, wpa);
        fma2(pA[6], a3.x, wpa); fma2(pA[7], a3.y, wpa);
        const ulonglong2* sb = (const ulonglong2*)(smat + (kc + L + 4) * 16);
        ulonglong2 b0 = sb[0], b1 = sb[1], b2 = sb[2], b3 = sb[3];
        fma2(pB[0], b0.x, wpb); fma2(pB[1], b0.y, wpb);
        fma2(pB[2], b1.x, wpb); fma2(pB[3], b1.y, wpb);
        fma2(pB[4], b2.x, wpb); fma2(pB[5], b2.y, wpb);
        fma2(pB[6], b3.x, wpb); fma2(pB[7], b3.y, wpb);
    }
}
template<int K>
__device__ __forceinline__ void gemm_col16(ull tot[8],
                                           const float* __restrict__ wj, int Hs,
                                           const float* __restrict__ smat) {
    ull c01[8], q[8], pA[8], pB[8];
    pass2<K, 0>(pA, pB, wj, Hs, smat);
    #pragma unroll
    for (int i = 0; i < 8; i++) c01[i] = add2(pA[i], pB[i]);
    pass2<K, 1>(pA, pB, wj, Hs, smat);
    #pragma unroll
    for (int i = 0; i < 8; i++) q[i] = add2(pA[i], pB[i]);
    #pragma unroll
    for (int i = 0; i < 8; i++) c01[i] = add2(c01[i], q[i]);
    pass2<K, 2>(pA, pB, wj, Hs, smat);
    #pragma unroll
    for (int i = 0; i < 8; i++) q[i] = add2(pA[i], pB[i]);
    pass2<K, 3>(pA, pB, wj, Hs, smat);
    #pragma unroll
    for (int i = 0; i < 8; i++) pA[i] = add2(pA[i], pB[i]);
    #pragma unroll
    for (int i = 0; i < 8; i++) q[i] = add2(q[i], pA[i]);
    #pragma unroll
    for (int i = 0; i < 8; i++) tot[i] = add2(c01[i], q[i]);
    constexpr int KMAIN = K & ~7;
    #pragma unroll
    for (int k = KMAIN; k < K; k++) {
        ull wp = pack2(__ldg(wj + (size_t)k * Hs));
        const ulonglong2* sp = (const ulonglong2*)(smat + k * 16);
        ulonglong2 v0 = sp[0], v1 = sp[1], v2 = sp[2], v3 = sp[3];
        fma2(tot[0], v0.x, wp); fma2(tot[1], v0.y, wp);
        fma2(tot[2], v1.x, wp); fma2(tot[3], v1.y, wp);
        fma2(tot[4], v2.x, wp); fma2(tot[5], v2.y, wp);
        fma2(tot[6], v3.x, wp); fma2(tot[7], v3.y, wp);
    }
}

// ================= C=2 channels x E=8 edges class-pair GEMM =================
// acc layout: acc[c*4 + u], c = channel (0,1), u = edge-pair (edges 2u, 2u+1 of slice).
// Per-(edge,channel) chains identical to R13 (ascending k within class, same tree).
template<int K, int L>
__device__ __forceinline__ void pass2_c2(ull pA[8], ull pB[8],
                                         const float* __restrict__ wj0, int Hs,
                                         const float* __restrict__ sm8) {
    #pragma unroll
    for (int i = 0; i < 8; i++) { pA[i] = 0; pB[i] = 0; }
    constexpr int KMAIN = K & ~7;
    #pragma unroll 2
    for (int kc = 0; kc < KMAIN; kc += 8) {
        float2 wL = __ldg((const float2*)(wj0 + (size_t)(kc + L) * Hs));
        float2 wM = __ldg((const float2*)(wj0 + (size_t)(kc + L + 4) * Hs));
        ull wL0 = pack2(wL.x), wL1 = pack2(wL.y);
        ull wM0 = pack2(wM.x), wM1 = pack2(wM.y);
        const ulonglong2* sa = (const ulonglong2*)(sm8 + (size_t)(kc + L) * 16);
        ulonglong2 a0 = sa[0], a1 = sa[1];
        fma2(pA[0], a0.x, wL0); fma2(pA[1], a0.y, wL0);
        fma2(pA[2], a1.x, wL0); fma2(pA[3], a1.y, wL0);
        fma2(pA[4], a0.x, wL1); fma2(pA[5], a0.y, wL1);
        fma2(pA[6], a1.x, wL1); fma2(pA[7], a1.y, wL1);
        const ulonglong2* sb = (const ulonglong2*)(sm8 + (size_t)(kc + L + 4) * 16);
        ulonglong2 b0 = sb[0], b1 = sb[1];
        fma2(pB[0], b0.x, wM0); fma2(pB[1], b0.y, wM0);
        fma2(pB[2], b1.x, wM0); fma2(pB[3], b1.y, wM0);
        fma2(pB[4], b0.x, wM1); fma2(pB[5], b0.y, wM1);
        fma2(pB[6], b1.x, wM1); fma2(pB[7], b1.y, wM1);
    }
}
template<int K>
__device__ __forceinline__ void gemm_col8_c2(ull tot[8],
                                             const float* __restrict__ wj0, int Hs,
                                             const float* __restrict__ sm8) {
    ull c01[8], q[8], pA[8], pB[8];
    pass2_c2<K, 0>(pA, pB, wj0, Hs, sm8);
    #pragma unroll
    for (int i = 0; i < 8; i++) c01[i] = add2(pA[i], pB[i]);
    pass2_c2<K, 1>(pA, pB, wj0, Hs, sm8);
    #pragma unroll
    for (int i = 0; i < 8; i++) q[i] = add2(pA[i], pB[i]);
    #pragma unroll
    for (int i = 0; i < 8; i++) c01[i] = add2(c01[i], q[i]);
    pass2_c2<K, 2>(pA, pB, wj0, Hs, sm8);
    #pragma unroll
    for (int i = 0; i < 8; i++) q[i] = add2(pA[i], pB[i]);
    pass2_c2<K, 3>(pA, pB, wj0, Hs, sm8);
    #pragma unroll
    for (int i = 0; i < 8; i++) pA[i] = add2(pA[i], pB[i]);
    #pragma unroll
    for (int i = 0; i < 8; i++) q[i] = add2(q[i], pA[i]);
    #pragma unroll
    for (int i = 0; i < 8; i++) tot[i] = add2(c01[i], q[i]);
    constexpr int KMAIN = K & ~7;
    #pragma unroll
    for (int k = KMAIN; k < K; k++) {   // sequential scalar tail
        float2 wv = __ldg((const float2*)(wj0 + (size_t)k * Hs));
        ull w0 = pack2(wv.x), w1p = pack2(wv.y);
        const ulonglong2* sp = (const ulonglong2*)(sm8 + (size_t)k * 16);
        ulonglong2 v0 = sp[0], v1 = sp[1];
        fma2(tot[0], v0.x, w0);  fma2(tot[1], v0.y, w0);
        fma2(tot[2], v1.x, w0);  fma2(tot[3], v1.y, w0);
        fma2(tot[4], v0.x, w1p); fma2(tot[5], v0.y, w1p);
        fma2(tot[6], v1.x, w1p); fma2(tot[7], v1.y, w1p);
    }
}

// ===== split GEMM1 pass, C=2 x E=8 (FIN=192): xi prefix hoisted per point =====
// sxi2 = sxi + 2h (points 2h,2h+1, row stride 4); sm8 = sdx + 8h (row stride 16).
template<int L>
__device__ __forceinline__ void pass_split_c2(ull pA[8], ull pB[8],
                                              const float* __restrict__ wj0, int Hs,
                                              const float* __restrict__ sxi2,
                                              const float* __restrict__ sm8) {
    ull aA = 0, aB = 0, bA = 0, bB = 0;   // class L ch0/ch1, class L+4 ch0/ch1
    #pragma unroll 4
    for (int kc = 0; kc < 192; kc += 8) {
        float2 wL = __ldg((const float2*)(wj0 + (size_t)(kc + L) * Hs));
        float2 wM = __ldg((const float2*)(wj0 + (size_t)(kc + L + 4) * Hs));
        ull xiL = *(const ull*)(sxi2 + (kc + L) * 4);
        ull xiM = *(const ull*)(sxi2 + (kc + L + 4) * 4);
        fma2(aA, xiL, pack2(wL.x)); fma2(aB, xiL, pack2(wL.y));
        fma2(bA, xiM, pack2(wM.x)); fma2(bB, xiM, pack2(wM.y));
    }
    {
        float2 vA = unpack2(aA);   // .x -> point 2h (pairs 0,1), .y -> point 2h+1 (pairs 2,3)
        pA[0] = pack2(vA.x); pA[1] = pack2(vA.x);
        pA[2] = pack2(vA.y); pA[3] = pack2(vA.y);
        float2 vB = unpack2(aB);
        pA[4] = pack2(vB.x); pA[5] = pack2(vB.x);
        pA[6] = pack2(vB.y); pA[7] = pack2(vB.y);
        float2 uA = unpack2(bA);
        pB[0] = pack2(uA.x); pB[1] = pack2(uA.x);
        pB[2] = pack2(uA.y); pB[3] = pack2(uA.y);
        float2 uB = unpack2(bB);
        pB[4] = pack2(uB.x); pB[5] = pack2(uB.x);
        pB[6] = pack2(uB.y); pB[7] = pack2(uB.y);
    }
    const float* wj2 = wj0 + (size_t)192 * Hs;
    #pragma unroll 2
    for (int kc = 0; kc < 192; kc += 8) {
        float2 wL = __ldg((const float2*)(wj2 + (size_t)(kc + L) * Hs));
        float2 wM = __ldg((const float2*)(wj2 + (size_t)(kc + L + 4) * Hs));
        ull wL0 = pack2(wL.x), wL1 = pack2(wL.y);
        ull wM0 = pack2(wM.x), wM1 = pack2(wM.y);
        const ulonglong2* sa = (const ulonglong2*)(sm8 + (size_t)(kc + L) * 16);
        ulonglong2 a0 = sa[0], a1 = sa[1];
        fma2(pA[0], a0.x, wL0); fma2(pA[1], a0.y, wL0);
        fma2(pA[2], a1.x, wL0); fma2(pA[3], a1.y, wL0);
        fma2(pA[4], a0.x, wL1); fma2(pA[5], a0.y, wL1);
        fma2(pA[6], a1.x, wL1); fma2(pA[7], a1.y, wL1);
        const ulonglong2* sb = (const ulonglong2*)(sm8 + (size_t)(kc + L + 4) * 16);
        ulonglong2 b0 = sb[0], b1 = sb[1];
        fma2(pB[0], b0.x, wM0); fma2(pB[1], b0.y, wM0);
        fma2(pB[2], b1.x, wM0); fma2(pB[3], b1.y, wM0);
        fma2(pB[4], b0.x, wM1); fma2(pB[5], b0.y, wM1);
        fma2(pB[6], b1.x, wM1); fma2(pB[7], b1.y, wM1);
    }
}
__device__ __forceinline__ void gemm1_split_c2(ull tot[8],
                                               const float* __restrict__ wj0, int Hs,
                                               const float* __restrict__ sxi2,
                                               const float* __restrict__ sm8) {
    ull c01[8], q[8], pA[8], pB[8];
    pass_split_c2<0>(pA, pB, wj0, Hs, sxi2, sm8);
    #pragma unroll
    for (int i = 0; i < 8; i++) c01[i] = add2(pA[i], pB[i]);
    pass_split_c2<1>(pA, pB, wj0, Hs, sxi2, sm8);
    #pragma unroll
    for (int i = 0; i < 8; i++) q[i] = add2(pA[i], pB[i]);
    #pragma unroll
    for (int i = 0; i < 8; i++) c01[i] = add2(c01[i], q[i]);
    pass_split_c2<2>(pA, pB, wj0, Hs, sxi2, sm8);
    #pragma unroll
    for (int i = 0; i < 8; i++) q[i] = add2(pA[i], pB[i]);
    pass_split_c2<3>(pA, pB, wj0, Hs, sxi2, sm8);
    #pragma unroll
    for (int i = 0; i < 8; i++) pA[i] = add2(pA[i], pB[i]);
    #pragma unroll
    for (int i = 0; i < 8; i++) q[i] = add2(q[i], pA[i]);
    #pragma unroll
    for (int i = 0; i < 8; i++) tot[i] = add2(c01[i], q[i]);
    // K=384: no tail
}

// ---------------- conv1 EdgeConv (FIN=4): R13 path, 256 threads ----------------
__global__ void __launch_bounds__(256, 2)
edgeconv1_kernel(const float* __restrict__ feat,
                 const int* __restrict__ idx,
                 const float* __restrict__ w1, const float* __restrict__ b1,
                 const float* __restrict__ w2, const float* __restrict__ b2,
                 float* __restrict__ out) {
    constexpr int FIN = 4, H = 96, Cout = 192, F2 = 8;
    __shared__ __align__(16) float sf[F2 * 16];
    __shared__ __align__(16) float s[H * 16];
    __shared__ int nb[16];
    int m0 = blockIdx.x * 4;
    int tid = threadIdx.x;
    if (tid < 16) {
        int p = tid >> 2;
        int m = m0 + p;
        nb[tid] = (m & ~(NN - 1)) + idx[m * KNNK + (tid & 3)];
    }
    __syncthreads();
    if (tid < F2 * 16) {
        int e = tid & 15, k = tid >> 4;
        int p = e >> 2;
        float v;
        if (k < FIN) v = feat[(size_t)(m0 + p) * FIN + k];
        else {
            int kk = k - FIN;
            v = __fadd_rn(feat[(size_t)nb[e] * FIN + kk], -feat[(size_t)(m0 + p) * FIN + kk]);
        }
        sf[tid] = v;
    }
    __syncthreads();
    if (tid < H) {
        int j = tid;
        ull tot[8];
        gemm_col16<F2>(tot, w1 + j, H, sf);
        float bb = b1[j];
        #pragma unroll
        for (int u = 0; u < 4; u++) {
            float2 r0 = unpack2(tot[2 * u]);
            float2 r1 = unpack2(tot[2 * u + 1]);
            *(float4*)(s + j * 16 + 4 * u) =
                make_float4(leakyf(__fadd_rn(r0.x, bb)), leakyf(__fadd_rn(r0.y, bb)),
                            leakyf(__fadd_rn(r1.x, bb)), leakyf(__fadd_rn(r1.y, bb)));
        }
    }
    __syncthreads();
    if (tid < Cout) {
        int o = tid;
        ull tot[8];
        gemm_col16<H>(tot, w2 + o, Cout, s);
        float bb = b2[o];
        #pragma unroll
        for (int p = 0; p < 4; p++) {
            float2 x0 = unpack2(tot[2 * p]);
            float2 x1 = unpack2(tot[2 * p + 1]);
            float r = leakyf(x0.x + bb) + leakyf(x0.y + bb) +
                      leakyf(x1.x + bb) + leakyf(x1.y + bb);
            out[(size_t)(m0 + p) * Cout + o] = r;
        }
    }
}

// ---------------- heavy EdgeConv: 4 points/block, 256 threads, C=2 x E=8 ----------------
// thread = (channel-pair cp = tid>>1, half h = tid&1): channels 2cp,2cp+1;
// edges 8h..8h+7 = points 2h,2h+1. Chains bit-identical to R13.
__global__ void __launch_bounds__(256, 2)
edgeconv_split_kernel(const float* __restrict__ feat,
                      const int* __restrict__ idx,
                      const float* __restrict__ w1, const float* __restrict__ b1,
                      const float* __restrict__ w2, const float* __restrict__ b2,
                      float* __restrict__ out) {
    constexpr int FIN = 192, H = 252, Cout = 192;
    __shared__ __align__(16) float sxi[FIN * 4];    // [k*4 + p]
    __shared__ __align__(16) float sdx[FIN * 16];   // [k*16 + e]
    __shared__ __align__(16) float s[H * 16];       // [j*16 + e]
    __shared__ int nb[16];

    int m0 = blockIdx.x * 4;
    int tid = threadIdx.x;

    if (tid < 16) {
        int p = tid >> 2;
        int m = m0 + p;
        nb[tid] = (m & ~(NN - 1)) + idx[m * KNNK + (tid & 3)];
    }
    __syncthreads();

    for (int t = tid; t < FIN * 4; t += 256) {
        int p = t & 3, k = t >> 2;
        sxi[t] = feat[(size_t)(m0 + p) * FIN + k];
    }
    #pragma unroll 2
    for (int t = tid; t < FIN * 16; t += 256) {
        int e = t & 15, k = t >> 4;
        int p = e >> 2;
        sdx[t] = __fadd_rn(feat[(size_t)nb[e] * FIN + k], -feat[(size_t)(m0 + p) * FIN + k]);
    }
    __syncthreads();

    int cp = tid >> 1, h = tid & 1;

    // GEMM 1 (split, C=2 x E=8): s = leaky(e @ w1 + b1)
    if (cp < H / 2) {
        int j0 = 2 * cp;
        ull tot[8];
        gemm1_split_c2(tot, w1 + j0, H, sxi + 2 * h, sdx + 8 * h);
        float bA = b1[j0], bB = b1[j0 + 1];
        // channel 0: tot[0..3] (pairs), channel 1: tot[4..7]
        float2 a0 = unpack2(tot[0]), a1 = unpack2(tot[1]);
        float2 a2 = unpack2(tot[2]), a3 = unpack2(tot[3]);
        *(float4*)(s + j0 * 16 + 8 * h) =
            make_float4(leakyf(__fadd_rn(a0.x, bA)), leakyf(__fadd_rn(a0.y, bA)),
                        leakyf(__fadd_rn(a1.x, bA)), leakyf(__fadd_rn(a1.y, bA)));
        *(float4*)(s + j0 * 16 + 8 * h + 4) =
            make_float4(leakyf(__fadd_rn(a2.x, bA)), leakyf(__fadd_rn(a2.y, bA)),
                        leakyf(__fadd_rn(a3.x, bA)), leakyf(__fadd_rn(a3.y, bA)));
        float2 c0 = unpack2(tot[4]), c1 = unpack2(tot[5]);
        float2 c2 = unpack2(tot[6]), c3 = unpack2(tot[7]);
        *(float4*)(s + (j0 + 1) * 16 + 8 * h) =
            make_float4(leakyf(__fadd_rn(c0.x, bB)), leakyf(__fadd_rn(c0.y, bB)),
                        leakyf(__fadd_rn(c1.x, bB)), leakyf(__fadd_rn(c1.y, bB)));
        *(float4*)(s + (j0 + 1) * 16 + 8 * h + 4) =
            make_float4(leakyf(__fadd_rn(c2.x, bB)), leakyf(__fadd_rn(c2.y, bB)),
                        leakyf(__fadd_rn(c3.x, bB)), leakyf(__fadd_rn(c3.y, bB)));
    }
    __syncthreads();

    // GEMM 2 (C=2 x E=8): out = sum_e leaky(s @ w2 + b2); points 2h, 2h+1
    if (cp < Cout / 2) {
        int o0 = 2 * cp;
        ull tot[8];
        gemm_col8_c2<H>(tot, w2 + o0, Cout, s + 8 * h);
        float bA = b2[o0], bB = b2[o0 + 1];
        #pragma unroll
        for (int pp = 0; pp < 2; pp++) {      // point 2h+pp, edge-pairs 2pp, 2pp+1
            float2 xA0 = unpack2(tot[2 * pp]);
            float2 xA1 = unpack2(tot[2 * pp + 1]);
            float rA = leakyf(xA0.x + bA) + leakyf(xA0.y + bA) +
                       leakyf(xA1.x + bA) + leakyf(xA1.y + bA);
            float2 xB0 = unpack2(tot[4 + 2 * pp]);
            float2 xB1 = unpack2(tot[4 + 2 * pp + 1]);
            float rB = leakyf(xB0.x + bB) + leakyf(xB0.y + bB) +
                       leakyf(xB1.x + bB) + leakyf(xB1.y + bB);
            *(float2*)(out + (size_t)(m0 + 2 * h + pp) * Cout + o0) = make_float2(rA, rB);
        }
    }
}

// ---------------- nn1+nn2 fused: 16 points/block, 256 threads, C=2 x 8 points ----------------
// thread = (cp = tid>>1, h = tid&1): channels 2cp,2cp+1; points 8h..8h+7.
// Sequential ascending-k chains per (point,channel) — identical to R13.
__global__ void __launch_bounds__(256)
nn12_kernel(const float* __restrict__ x,
            const float* __restrict__ a, const float* __restrict__ b,
            const float* __restrict__ c, const float* __restrict__ d,
            const float* __restrict__ w1, const float* __restrict__ b1,
            const float* __restrict__ w2, const float* __restrict__ b2,
            float* __restrict__ hout) {
    extern __shared__ float dyn2_[];
    float* sin_ = dyn2_;               // [ch*16 + p]
    float* sh1  = dyn2_ + 772 * 16;    // [j*16 + p]
    int m0 = blockIdx.x * 16;
    int tid = threadIdx.x;
    #pragma unroll 4
    for (int e = tid; e < 772 * 16; e += 256) {
        int ch = e >> 4, p = e & 15;
        size_t mp = (size_t)(m0 + p);
        float val;
        if (ch < 4)        val = x[mp * 4 + ch];
        else if (ch < 196) val = a[mp * 192 + (ch - 4)];
        else if (ch < 388) val = b[mp * 192 + (ch - 196)];
        else if (ch < 580) val = c[mp * 192 + (ch - 388)];
        else               val = d[mp * 192 + (ch - 580)];
        sin_[e] = val;
    }
    __syncthreads();
    int cp = tid >> 1, h = tid & 1;
    if (cp < 126) {
        int j0 = 2 * cp;
        ull acc[8];
        #pragma unroll
        for (int i = 0; i < 8; i++) acc[i] = 0;
        #pragma unroll 2
        for (int k = 0; k < 772; k++) {
            float2 wv = __ldg((const float2*)(w1 + (size_t)k * 252 + j0));
            ull w0 = pack2(wv.x), w1p = pack2(wv.y);
            const ulonglong2* sp = (const ulonglong2*)(sin_ + k * 16 + 8 * h);
            ulonglong2 s0 = sp[0], s1 = sp[1];
            fma2(acc[0], s0.x, w0);  fma2(acc[1], s0.y, w0);
            fma2(acc[2], s1.x, w0);  fma2(acc[3], s1.y, w0);
            fma2(acc[4], s0.x, w1p); fma2(acc[5], s0.y, w1p);
            fma2(acc[6], s1.x, w1p); fma2(acc[7], s1.y, w1p);
        }
        float bA = b1[j0], bB = b1[j0 + 1];
        float2 r0 = unpack2(acc[0]), r1 = unpack2(acc[1]);
        float2 r2 = unpack2(acc[2]), r3 = unpack2(acc[3]);
        *(float4*)(sh1 + j0 * 16 + 8 * h) =
            make_float4(leakyf(r0.x + bA), leakyf(r0.y + bA),
                        leakyf(r1.x + bA), leakyf(r1.y + bA));
        *(float4*)(sh1 + j0 * 16 + 8 * h + 4) =
            make_float4(leakyf(r2.x + bA), leakyf(r2.y + bA),
                        leakyf(r3.x + bA), leakyf(r3.y + bA));
        float2 t0 = unpack2(acc[4]), t1 = unpack2(acc[5]);
        float2 t2 = unpack2(acc[6]), t3 = unpack2(acc[7]);
        *(float4*)(sh1 + (j0 + 1) * 16 + 8 * h) =
            make_float4(leakyf(t0.x + bB), leakyf(t0.y + bB),
                        leakyf(t1.x + bB), leakyf(t1.y + bB));
        *(float4*)(sh1 + (j0 + 1) * 16 + 8 * h + 4) =
            make_float4(leakyf(t2.x + bB), leakyf(t2.y + bB),
                        leakyf(t3.x + bB), leakyf(t3.y + bB));
    }
    __syncthreads();
    if (cp < 96) {
        int o0 = 2 * cp;
        ull acc[8];
        #pragma unroll
        for (int i = 0; i < 8; i++) acc[i] = 0;
        #pragma unroll 2
        for (int mm = 0; mm < 252; mm++) {
            float2 wv = __ldg((const float2*)(w2 + (size_t)mm * 192 + o0));
            ull w0 = pack2(wv.x), w1p = pack2(wv.y);
            const ulonglong2* sp = (const ulonglong2*)(sh1 + mm * 16 + 8 * h);
            ulonglong2 s0 = sp[0], s1 = sp[1];
            fma2(acc[0], s0.x, w0);  fma2(acc[1], s0.y, w0);
            fma2(acc[2], s1.x, w0);  fma2(acc[3], s1.y, w0);
            fma2(acc[4], s0.x, w1p); fma2(acc[5], s0.y, w1p);
            fma2(acc[6], s1.x, w1p); fma2(acc[7], s1.y, w1p);
        }
        float bA = b2[o0], bB = b2[o0 + 1];
        #pragma unroll
        for (int u = 0; u < 4; u++) {         // pair u -> points 8h+2u, 8h+2u+1
            float2 rA = unpack2(acc[u]);
            float2 rB = unpack2(acc[4 + u]);
            *(float2*)(hout + (size_t)(m0 + 8 * h + 2 * u) * 192 + o0) =
                make_float2(rA.x + bA, rB.x + bB);
            *(float2*)(hout + (size_t)(m0 + 8 * h + 2 * u + 1) * 192 + o0) =
                make_float2(rA.y + bA, rB.y + bB);
        }
    }
}

// ---------------- pooling (unchanged) ----------------
__global__ void pool_kernel(const float* __restrict__ h, float* __restrict__ pooled) {
    int b = blockIdx.x, cch = threadIdx.x;
    const float* hp = h + (size_t)b * NN * 192 + cch;
    float mx = -1e38f, mn = 1e38f;
    double sm = 0.0;
    #pragma unroll 4
    for (int n = 0; n < NN; n++) {
        float v = hp[(size_t)n * 192];
        mx = fmaxf(mx, v); mn = fminf(mn, v);
        sm += (double)v;
    }
    float smf = (float)sm;
    float* pb = pooled + b * 768;
    pb[cch]       = leakyf(mx);
    pb[192 + cch] = leakyf(mn);
    pb[384 + cch] = leakyf(smf);
    pb[576 + cch] = leakyf(__fmul_rn(smf, (1.0f / 256.0f)));
}

// ---------------- final head (unchanged) ----------------
__global__ void final_kernel(const float* __restrict__ pooled,
                             const float* __restrict__ w3, const float* __restrict__ b3,
                             const float* __restrict__ w4, const float* __restrict__ b4,
                             float* __restrict__ out) {
    __shared__ float sp[768];
    __shared__ float smid[96];
    int b = blockIdx.x, tid = threadIdx.x;
    for (int e = tid; e < 768; e += blockDim.x) sp[e] = pooled[b * 768 + e];
    __syncthreads();
    if (tid < 96) {
        float acc = 0.f;
        for (int k = 0; k < 768; k++) acc = fmaf(sp[k], w3[k * 96 + tid], acc);
        smid[tid] = leakyf(acc + b3[tid]);
    }
    __syncthreads();
    if (tid == 0) {
        float sacc = 0.f;
        for (int k = 0; k < 96; k++) sacc = fmaf(smid[k], w4[k], sacc);
        out[b] = sacc + b4[0];
    }
}

// ---------------- launch ----------------
extern "C" void kernel_launch(void* const* d_in, const int* in_sizes, int n_in,
                              void* d_out, int out_size) {
    const float* x = (const float*)d_in[0];
    const float* prm[24];
    for (int i = 0; i < 24; i++) prm[i] = (const float*)d_in[i + 1];

    float *ga, *gb, *gc, *gd, *gh, *gp;
    int* gi;
    cudaGetSymbolAddress((void**)&ga, g_a);
    cudaGetSymbolAddress((void**)&gb, g_b);
    cudaGetSymbolAddress((void**)&gc, g_c);
    cudaGetSymbolAddress((void**)&gd, g_d);
    cudaGetSymbolAddress((void**)&gh, g_h);
    cudaGetSymbolAddress((void**)&gp, g_pool);
    cudaGetSymbolAddress((void**)&gi, g_idx);

    int nn12_smem = (772 + 252) * 16 * 4;   // 65536 B
    cudaFuncSetAttribute(nn12_kernel, cudaFuncAttributeMaxDynamicSharedMemorySize, nn12_smem);

    knn_kernel<<<BB, NN>>>(x, 4, gi);
    edgeconv1_kernel<<<NPTS / 4, 256>>>(x, gi, prm[0], prm[1], prm[2], prm[3], ga);

    knn_kernel<<<BB, NN>>>(ga, 192, gi);
    edgeconv_split_kernel<<<NPTS / 4, 256>>>(ga, gi, prm[4], prm[5], prm[6], prm[7], gb);

    knn_kernel<<<BB, NN>>>(gb, 192, gi);
    edgeconv_split_kernel<<<NPTS / 4, 256>>>(gb, gi, prm[8], prm[9], prm[10], prm[11], gc);

    knn_kernel<<<BB, NN>>>(gc, 192, gi);
    edgeconv_split_kernel<<<NPTS / 4, 256>>>(gc, gi, prm[12], prm[13], prm[14], prm[15], gd);

    nn12_kernel<<<NPTS / 16, 256, nn12_smem>>>(x, ga, gb, gc, gd,
                                               prm[16], prm[17], prm[18], prm[19], gh);

    pool_kernel<<<BB, 192>>>(gh, gp);
    final_kernel<<<BB, 128>>>(gp, prm[20], prm[21], prm[22], prm[23], (float*)d_out);
}